// round 2
// baseline (speedup 1.0000x reference)
#include <cuda_runtime.h>
#include <cuda_bf16.h>
#include <cstdint>

// Sizes
#define BB 128
#define TT 256
#define DD 256
#define UU 1024
#define N2 2048   // 2*U

// Scratch (device globals -- no cudaMalloc allowed)
__device__ float g_xpre[(size_t)BB * TT * N2];      // 256 MB: x@Wx + b, [B*T, 2U]
__device__ float g_h[2][BB * UU];                   // ping-pong hidden state
__device__ float g_wpack[32 * 1024 * 64];           // Wh repacked per col-group
__device__ float g_tau[UU];                         // softplus(w_tau)

// ---------------------------------------------------------------------------
// Setup kernels
// ---------------------------------------------------------------------------
__global__ void tau_kernel(const float* __restrict__ w_tau) {
    int u = blockIdx.x * blockDim.x + threadIdx.x;
    if (u < UU) g_tau[u] = log1pf(expf(w_tau[u]));
}

__global__ void init_h_kernel(const float* __restrict__ h0) {
    int i = blockIdx.x * blockDim.x + threadIdx.x;
    if (i < BB * UU) g_h[0][i] = h0[i];
}

// Repack Wh[1024][2048] into 32 col-group slabs:
// wpack[g][k][j]: j<32 -> Wh[k][g*32+j] (f cols); j>=32 -> Wh[k][1024+g*32+j-32]
__global__ void repack_kernel(const float* __restrict__ Wh) {
    int idx = blockIdx.x * blockDim.x + threadIdx.x;   // 0 .. 2M-1
    if (idx >= 32 * 1024 * 64) return;
    int j = idx & 63;
    int k = (idx >> 6) & 1023;
    int g = idx >> 16;
    int col = (j < 32) ? (g * 32 + j) : (1024 + g * 32 + (j - 32));
    g_wpack[idx] = Wh[k * N2 + col];
}

// ---------------------------------------------------------------------------
// xpre GEMM: XP[i,n] = sum_d F[i,d]*Wx[d,n] + b[n];  M=32768, N=2048, K=256
// Block tile 128x64, 256 threads, micro 8x4.
// ---------------------------------------------------------------------------
__global__ void __launch_bounds__(256) xpre_gemm_kernel(
    const float* __restrict__ F, const float* __restrict__ Wx,
    const float* __restrict__ bias) {
    __shared__ float As[32][129];
    __shared__ float Bs[32][64];

    int tid = threadIdx.x;
    int bm = blockIdx.y;            // 0..255
    int bn = blockIdx.x;            // 0..31
    int mg = tid >> 4;              // 0..15
    int ng = tid & 15;              // 0..15
    int m0 = mg * 8;
    int n0 = ng * 4;

    const float* Ablk = F + (size_t)bm * 128 * DD;
    const float* Bcol = Wx + bn * 64;

    float acc[8][4];
#pragma unroll
    for (int i = 0; i < 8; i++)
#pragma unroll
        for (int j = 0; j < 4; j++) acc[i][j] = 0.0f;

    for (int k0 = 0; k0 < DD; k0 += 32) {
#pragma unroll
        for (int j = 0; j < 4; j++) {
            int v = tid + 256 * j;
            int kq = v & 7, m = v >> 3;
            float4 a4 = *(const float4*)(Ablk + (size_t)m * DD + k0 + kq * 4);
            As[kq * 4 + 0][m] = a4.x;
            As[kq * 4 + 1][m] = a4.y;
            As[kq * 4 + 2][m] = a4.z;
            As[kq * 4 + 3][m] = a4.w;
        }
#pragma unroll
        for (int j = 0; j < 2; j++) {
            int v = tid + 256 * j;
            int nq = v & 15, k = v >> 4;
            *(float4*)(&Bs[k][nq * 4]) =
                *(const float4*)(Bcol + (size_t)(k0 + k) * N2 + nq * 4);
        }
        __syncthreads();

#pragma unroll 8
        for (int k = 0; k < 32; k++) {
            float bv[4];
            *(float4*)bv = *(const float4*)(&Bs[k][n0]);
            float av[8];
#pragma unroll
            for (int i = 0; i < 8; i++) av[i] = As[k][m0 + i];
#pragma unroll
            for (int i = 0; i < 8; i++)
#pragma unroll
                for (int j = 0; j < 4; j++) acc[i][j] += av[i] * bv[j];
        }
        __syncthreads();
    }

    int nbase = bn * 64 + n0;
    float bv[4];
    *(float4*)bv = *(const float4*)(bias + nbase);
#pragma unroll
    for (int i = 0; i < 8; i++) {
        size_t row = (size_t)bm * 128 + m0 + i;
        float4 o;
        o.x = acc[i][0] + bv[0];
        o.y = acc[i][1] + bv[1];
        o.z = acc[i][2] + bv[2];
        o.w = acc[i][3] + bv[3];
        *(float4*)(&g_xpre[row * N2 + nbase]) = o;
    }
}

// ---------------------------------------------------------------------------
// Per-step kernel: 128 blocks x 256 threads. Block = (row-tile bm in 0..3,
// col-group g in 0..31). Computes pre_f/pre_a for 32 rows x 32 u's, applies
// the LTC cell, writes h_next and out[:, t, :].
// Cross-step ordering comes from stream ordering of launches.
// ---------------------------------------------------------------------------
__global__ void __launch_bounds__(256) step_kernel(
    int t,
    const float* __restrict__ time_steps,   // [B, T]
    float* __restrict__ out) {              // [B, T, U]
    __shared__ float hs[32][40];            // [m][k], padded (160B rows, 16B-aligned)
    __shared__ float ws[32][64];            // [k][j]

    int tid = threadIdx.x;
    int blk = blockIdx.x;
    int bm = blk & 3;            // row tile (32 rows)
    int g  = blk >> 2;           // col group (32 u's)
    int row0 = bm * 32;

    const float* hc = g_h[t & 1];
    float* hn = g_h[(t + 1) & 1];
    const float* wblk = g_wpack + (size_t)g * 1024 * 64;

    int ng = tid & 31;           // u within group
    int mg = tid >> 5;           // 0..7
    int m0 = mg * 4;

    float accf[4] = {0.f, 0.f, 0.f, 0.f};
    float acca[4] = {0.f, 0.f, 0.f, 0.f};

    for (int k0 = 0; k0 < UU; k0 += 32) {
        // Stage h tile [32 rows x 32 k], natural layout. tid -> (m, kq):
        // warp has m 0..3, kq 0..7 -> 128B-contiguous LDG per m group.
        {
            int m = tid >> 3, kq = tid & 7;
            float4 h4 = *(const float4*)(hc + (size_t)(row0 + m) * UU + k0 + kq * 4);
            *(float4*)(&hs[m][kq * 4]) = h4;
        }
        // Stage w chunk [32 k x 64 j] = 2048 floats, flat float4 copy.
        {
            const float4* src = (const float4*)(wblk + (size_t)k0 * 64);
            float4* dst = (float4*)ws;
            dst[tid]       = src[tid];
            dst[tid + 256] = src[tid + 256];
        }
        __syncthreads();

#pragma unroll
        for (int k = 0; k < 32; k++) {
            float wf = ws[k][ng];          // conflict-free (stride 64 rows)
            float wa = ws[k][ng + 32];
#pragma unroll
            for (int i = 0; i < 4; i++) {
                float hv = hs[m0 + i][k];  // warp-broadcast
                accf[i] = fmaf(hv, wf, accf[i]);
                acca[i] = fmaf(hv, wa, acca[i]);
            }
        }
        __syncthreads();
    }

    // LTC epilogue: thread owns rows row0+m0..+3, u = g*32+ng
    int u = g * 32 + ng;
    float tau = g_tau[u];
#pragma unroll
    for (int i = 0; i < 4; i++) {
        int b = row0 + m0 + i;
        float dt = time_steps[b * TT + t];
        size_t xb = ((size_t)b * TT + t) * N2 + u;
        float pf = accf[i] + g_xpre[xb];
        float pa = acca[i] + g_xpre[xb + UU];
        float f = 1.0f / (1.0f + expf(-pf));
        float a = tanhf(pa);
        float hprev = hc[(size_t)b * UU + u];
        float decay = expf(-dt * (tau + f));
        float hnew = (hprev - a) * decay + a;
        hn[(size_t)b * UU + u] = hnew;
        out[((size_t)b * TT + t) * UU + u] = hnew;
    }
}

// ---------------------------------------------------------------------------
// Launch
// ---------------------------------------------------------------------------
extern "C" void kernel_launch(void* const* d_in, const int* in_sizes, int n_in,
                              void* d_out, int out_size) {
    const float* features   = (const float*)d_in[0];   // [B,T,D]
    const float* time_steps = (const float*)d_in[1];   // [B,T]
    const float* Wx         = (const float*)d_in[2];   // [D,2U]
    const float* Wh         = (const float*)d_in[3];   // [U,2U]
    const float* bias       = (const float*)d_in[4];   // [2U]
    const float* w_tau      = (const float*)d_in[5];   // [U]
    const float* h0         = (const float*)d_in[6];   // [B,U]
    float* out = (float*)d_out;                        // [B,T,U]

    tau_kernel<<<4, 256>>>(w_tau);
    repack_kernel<<<(32 * 1024 * 64 + 1023) / 1024, 1024>>>(Wh);
    init_h_kernel<<<(BB * UU + 255) / 256, 256>>>(h0);
    xpre_gemm_kernel<<<dim3(32, 256), 256>>>(features, Wx, bias);

    for (int t = 0; t < TT; t++) {
        step_kernel<<<128, 256>>>(t, time_steps, out);
    }
}

// round 5
// speedup vs baseline: 1.2359x; 1.2359x over previous
#include <cuda_runtime.h>
#include <cuda_bf16.h>
#include <cstdint>

// Sizes
#define BB 128
#define TT 256
#define DD 256
#define UU 1024
#define N2 2048

// Recurrent-kernel geometry
#define NGRP 64            // blocks; block owns 16 u's -> N=32 cols (16 f + 16 a)
#define NT 32
#define BPAD 1032          // B smem row stride in elems (1024 + 8 pad -> bank-free)
#define SMEM_BYTES (2 * 32 * BPAD * 2)   // hi+lo matrices, bf16

// ---------------------------------------------------------------------------
// Device scratch (no cudaMalloc allowed)
// ---------------------------------------------------------------------------
__device__ float g_xpre[(size_t)BB * TT * N2];          // x@Wx + b
__device__ float g_h[2][BB * UU];                       // fp32 hidden, ping-pong
__device__ __nv_bfloat16 g_hhi[2][BB * UU];
__device__ __nv_bfloat16 g_hlo[2][BB * UU];
__device__ __nv_bfloat16 g_whi[NGRP * NT * UU];         // Wh repack hi [g][n][k]
__device__ __nv_bfloat16 g_wlo[NGRP * NT * UU];         // Wh repack lo
__device__ float g_tau[UU];

// ---------------------------------------------------------------------------
// mma.sync m16n8k16 bf16 (baseline sm_80+ instruction; compiles for sm_103)
// ---------------------------------------------------------------------------
__device__ __forceinline__ void mma16816(float4& d, const uint32_t* a,
                                         const uint32_t* b) {
    asm volatile(
        "mma.sync.aligned.m16n8k16.row.col.f32.bf16.bf16.f32 "
        "{%0,%1,%2,%3}, {%4,%5,%6,%7}, {%8,%9}, {%0,%1,%2,%3};"
        : "+f"(d.x), "+f"(d.y), "+f"(d.z), "+f"(d.w)
        : "r"(a[0]), "r"(a[1]), "r"(a[2]), "r"(a[3]), "r"(b[0]), "r"(b[1]));
}

// ---------------------------------------------------------------------------
// Setup kernels
// ---------------------------------------------------------------------------
__global__ void tau_kernel(const float* __restrict__ w_tau) {
    int u = blockIdx.x * blockDim.x + threadIdx.x;
    if (u < UU) g_tau[u] = log1pf(expf(w_tau[u]));
}

__global__ void init_h_kernel(const float* __restrict__ h0) {
    int i = blockIdx.x * blockDim.x + threadIdx.x;
    if (i >= BB * UU) return;
    float v = h0[i];
    g_h[0][i] = v;
    __nv_bfloat16 hi = __float2bfloat16(v);
    g_hhi[0][i] = hi;
    g_hlo[0][i] = __float2bfloat16(v - __bfloat162float(hi));
}

// Wh split+repack: [g][n][k]; n<16 -> f col u=g*16+n; n>=16 -> a col 1024+g*16+n-16
__global__ void wsplit_kernel(const float* __restrict__ Wh) {
    int idx = blockIdx.x * blockDim.x + threadIdx.x;
    if (idx >= NGRP * NT * UU) return;
    int k = idx & (UU - 1);
    int n = (idx >> 10) & (NT - 1);
    int g = idx >> 15;
    int col = (n < 16) ? (g * 16 + n) : (UU + g * 16 + (n - 16));
    float v = Wh[(size_t)k * N2 + col];
    __nv_bfloat16 hi = __float2bfloat16(v);
    g_whi[idx] = hi;
    g_wlo[idx] = __float2bfloat16(v - __bfloat162float(hi));
}

// ---------------------------------------------------------------------------
// xpre GEMM (fp32, known-good): M=32768, N=2048, K=256
// ---------------------------------------------------------------------------
__global__ void __launch_bounds__(256) xpre_gemm_kernel(
    const float* __restrict__ F, const float* __restrict__ Wx,
    const float* __restrict__ bias) {
    __shared__ float As[32][129];
    __shared__ float Bs[32][64];

    int tid = threadIdx.x;
    int bm = blockIdx.y, bn = blockIdx.x;
    int mg = tid >> 4, ng = tid & 15;
    int m0 = mg * 8, n0 = ng * 4;

    const float* Ablk = F + (size_t)bm * 128 * DD;
    const float* Bcol = Wx + bn * 64;

    float acc[8][4];
#pragma unroll
    for (int i = 0; i < 8; i++)
#pragma unroll
        for (int j = 0; j < 4; j++) acc[i][j] = 0.0f;

    for (int k0 = 0; k0 < DD; k0 += 32) {
#pragma unroll
        for (int j = 0; j < 4; j++) {
            int v = tid + 256 * j;
            int kq = v & 7, m = v >> 3;
            float4 a4 = *(const float4*)(Ablk + (size_t)m * DD + k0 + kq * 4);
            As[kq * 4 + 0][m] = a4.x;
            As[kq * 4 + 1][m] = a4.y;
            As[kq * 4 + 2][m] = a4.z;
            As[kq * 4 + 3][m] = a4.w;
        }
#pragma unroll
        for (int j = 0; j < 2; j++) {
            int v = tid + 256 * j;
            int nq = v & 15, k = v >> 4;
            *(float4*)(&Bs[k][nq * 4]) =
                *(const float4*)(Bcol + (size_t)(k0 + k) * N2 + nq * 4);
        }
        __syncthreads();
#pragma unroll 8
        for (int k = 0; k < 32; k++) {
            float bv[4];
            *(float4*)bv = *(const float4*)(&Bs[k][n0]);
            float av[8];
#pragma unroll
            for (int i = 0; i < 8; i++) av[i] = As[k][m0 + i];
#pragma unroll
            for (int i = 0; i < 8; i++)
#pragma unroll
                for (int j = 0; j < 4; j++) acc[i][j] += av[i] * bv[j];
        }
        __syncthreads();
    }
    int nbase = bn * 64 + n0;
    float bv[4];
    *(float4*)bv = *(const float4*)(bias + nbase);
#pragma unroll
    for (int i = 0; i < 8; i++) {
        size_t row = (size_t)bm * 128 + m0 + i;
        float4 o;
        o.x = acc[i][0] + bv[0];
        o.y = acc[i][1] + bv[1];
        o.z = acc[i][2] + bv[2];
        o.w = acc[i][3] + bv[3];
        *(float4*)(&g_xpre[row * N2 + nbase]) = o;
    }
}

// ---------------------------------------------------------------------------
// Recurrent step kernel (mma.sync, split-bf16, k-split across warp halves)
// 64 blocks x 256 threads. Warp w: m-warp = w&3 (rows m0..m0+31),
// k-half = w>>2 (k in [half*512, half*512+512)). Warp tile 32m x 32n.
// ---------------------------------------------------------------------------
__global__ void __launch_bounds__(256, 1) step_kernel(
    int t, const float* __restrict__ ts, float* __restrict__ out) {
    extern __shared__ __nv_bfloat16 Bs[];   // [2 (hi/lo)][32 n][BPAD k]

    int tid = threadIdx.x;
    int wid = tid >> 5, lane = tid & 31;
    int g = blockIdx.x;
    int cur = t & 1, nxt = cur ^ 1;

    // ---- Stage Wh slab (hi+lo) into smem: 128KB, once per step ----
    {
        const __nv_bfloat16* wh = g_whi + (size_t)g * NT * UU;
        const __nv_bfloat16* wl = g_wlo + (size_t)g * NT * UU;
#pragma unroll
        for (int i = 0; i < 16; i++) {
            int c = tid + i * 256;             // 0..4095: n = c>>7, kc = c&127
            int n = c >> 7, kc = c & 127;
            *(uint4*)(Bs + n * BPAD + kc * 8) =
                *(const uint4*)(wh + n * 1024 + kc * 8);
            *(uint4*)(Bs + 32 * BPAD + n * BPAD + kc * 8) =
                *(const uint4*)(wl + n * 1024 + kc * 8);
        }
    }
    __syncthreads();

    int mw = wid & 3;
    int hf = wid >> 2;
    int r0 = mw * 32 + (lane >> 2);
    int kb = hf * 512 + (lane & 3) * 2;

    const char* ahp = (const char*)g_hhi[cur] + ((size_t)r0 * UU + kb) * 2;
    const char* alp = (const char*)g_hlo[cur] + ((size_t)r0 * UU + kb) * 2;
    const __nv_bfloat16* bsf = Bs + (lane >> 2) * BPAD + hf * 512 + (lane & 3) * 2;

    float4 acc[2][4];
#pragma unroll
    for (int mt = 0; mt < 2; mt++)
#pragma unroll
        for (int nt = 0; nt < 4; nt++) acc[mt][nt] = make_float4(0.f, 0.f, 0.f, 0.f);

    // A regs: [buf][sub(k16 within k32)][mtile][4]
    uint32_t ah[2][2][2][4], al[2][2][2][4];

#define LOADA32(KS2, BUF)                                                       \
    do {                                                                        \
        _Pragma("unroll") for (int sub = 0; sub < 2; sub++) {                   \
            _Pragma("unroll") for (int mt = 0; mt < 2; mt++) {                  \
                const char* p = ahp + mt * 16 * 2048 + ((KS2) * 2 + sub) * 32;  \
                ah[BUF][sub][mt][0] = *(const uint32_t*)p;                      \
                ah[BUF][sub][mt][1] = *(const uint32_t*)(p + 8 * 2048);         \
                ah[BUF][sub][mt][2] = *(const uint32_t*)(p + 16);               \
                ah[BUF][sub][mt][3] = *(const uint32_t*)(p + 8 * 2048 + 16);    \
                const char* q = alp + mt * 16 * 2048 + ((KS2) * 2 + sub) * 32;  \
                al[BUF][sub][mt][0] = *(const uint32_t*)q;                      \
                al[BUF][sub][mt][1] = *(const uint32_t*)(q + 8 * 2048);         \
                al[BUF][sub][mt][2] = *(const uint32_t*)(q + 16);               \
                al[BUF][sub][mt][3] = *(const uint32_t*)(q + 8 * 2048 + 16);    \
            }                                                                   \
        }                                                                       \
    } while (0)

    LOADA32(0, 0);

#pragma unroll 2
    for (int ks2 = 0; ks2 < 16; ks2++) {
        int b = ks2 & 1;
        if (ks2 < 15) LOADA32(ks2 + 1, b ^ 1);
#pragma unroll
        for (int sub = 0; sub < 2; sub++) {
            int ks = ks2 * 2 + sub;
            uint32_t bh[4][2], bl[4][2];
#pragma unroll
            for (int nt = 0; nt < 4; nt++) {
                const __nv_bfloat16* bp = bsf + nt * 8 * BPAD + ks * 16;
                bh[nt][0] = *(const uint32_t*)bp;
                bh[nt][1] = *(const uint32_t*)(bp + 8);
                bl[nt][0] = *(const uint32_t*)(bp + 32 * BPAD);
                bl[nt][1] = *(const uint32_t*)(bp + 32 * BPAD + 8);
            }
#pragma unroll
            for (int mt = 0; mt < 2; mt++)
#pragma unroll
                for (int nt = 0; nt < 4; nt++) {
                    mma16816(acc[mt][nt], ah[b][sub][mt], bh[nt]);
                    mma16816(acc[mt][nt], ah[b][sub][mt], bl[nt]);
                    mma16816(acc[mt][nt], al[b][sub][mt], bh[nt]);
                }
        }
    }

    // ---- k-split reduction through smem (reuse B buffer) ----
    __syncthreads();
    float4* red = (float4*)Bs;
    if (wid >= 4) {
        float4* rp = red + (size_t)(wid - 4) * 288 + lane * 9;   // 36 floats/lane
#pragma unroll
        for (int mt = 0; mt < 2; mt++)
#pragma unroll
            for (int nt = 0; nt < 4; nt++) rp[mt * 4 + nt] = acc[mt][nt];
    }
    __syncthreads();

    if (wid < 4) {
        const float4* rp = red + (size_t)wid * 288 + lane * 9;
#pragma unroll
        for (int mt = 0; mt < 2; mt++)
#pragma unroll
            for (int nt = 0; nt < 4; nt++) {
                float4 r4 = rp[mt * 4 + nt];
                acc[mt][nt].x += r4.x;
                acc[mt][nt].y += r4.y;
                acc[mt][nt].z += r4.z;
                acc[mt][nt].w += r4.w;
            }

        // ---- LTC epilogue: thread-local f/a pairing ----
        int u0 = g * 16;
#pragma unroll
        for (int mt = 0; mt < 2; mt++) {
#pragma unroll
            for (int rr = 0; rr < 2; rr++) {
                int row = wid * 32 + mt * 16 + (lane >> 2) + rr * 8;
                float dt = ts[row * TT + t];
#pragma unroll
                for (int nt = 0; nt < 2; nt++) {
                    int ul = nt * 8 + (lane & 3) * 2;
                    int u = u0 + ul;
                    size_t xb = ((size_t)row * TT + t) * N2 + u;
                    float2 xf = *(const float2*)(g_xpre + xb);
                    float2 xa = *(const float2*)(g_xpre + xb + UU);
                    float2 tv = *(const float2*)(g_tau + u);
                    float2 hp = *(const float2*)(g_h[cur] + (size_t)row * UU + u);

                    float pre_f0, pre_a0, pre_f1, pre_a1;
                    if (rr == 0) {
                        pre_f0 = acc[mt][nt].x;     pre_f1 = acc[mt][nt].y;
                        pre_a0 = acc[mt][nt + 2].x; pre_a1 = acc[mt][nt + 2].y;
                    } else {
                        pre_f0 = acc[mt][nt].z;     pre_f1 = acc[mt][nt].w;
                        pre_a0 = acc[mt][nt + 2].z; pre_a1 = acc[mt][nt + 2].w;
                    }
                    pre_f0 += xf.x; pre_f1 += xf.y;
                    pre_a0 += xa.x; pre_a1 += xa.y;

                    float f0 = 1.0f / (1.0f + expf(-pre_f0));
                    float f1 = 1.0f / (1.0f + expf(-pre_f1));
                    float a0 = tanhf(pre_a0);
                    float a1 = tanhf(pre_a1);
                    float d0 = expf(-dt * (tv.x + f0));
                    float d1 = expf(-dt * (tv.y + f1));
                    float h0n = (hp.x - a0) * d0 + a0;
                    float h1n = (hp.y - a1) * d1 + a1;

                    *(float2*)(g_h[nxt] + (size_t)row * UU + u) =
                        make_float2(h0n, h1n);
                    *(float2*)(out + ((size_t)row * TT + t) * UU + u) =
                        make_float2(h0n, h1n);

                    __nv_bfloat16 hi0 = __float2bfloat16(h0n);
                    __nv_bfloat16 hi1 = __float2bfloat16(h1n);
                    __nv_bfloat162 hhi2;
                    hhi2.x = hi0; hhi2.y = hi1;
                    *(__nv_bfloat162*)(g_hhi[nxt] + (size_t)row * UU + u) = hhi2;
                    __nv_bfloat162 hlo2;
                    hlo2.x = __float2bfloat16(h0n - __bfloat162float(hi0));
                    hlo2.y = __float2bfloat16(h1n - __bfloat162float(hi1));
                    *(__nv_bfloat162*)(g_hlo[nxt] + (size_t)row * UU + u) = hlo2;
                }
            }
        }
    }
}

// ---------------------------------------------------------------------------
// Launch
// ---------------------------------------------------------------------------
extern "C" void kernel_launch(void* const* d_in, const int* in_sizes, int n_in,
                              void* d_out, int out_size) {
    const float* features   = (const float*)d_in[0];
    const float* time_steps = (const float*)d_in[1];
    const float* Wx         = (const float*)d_in[2];
    const float* Wh         = (const float*)d_in[3];
    const float* bias       = (const float*)d_in[4];
    const float* w_tau      = (const float*)d_in[5];
    const float* h0         = (const float*)d_in[6];
    float* out = (float*)d_out;

    // >48KB dynamic smem opt-in (attribute call, not a stream op; idempotent)
    cudaFuncSetAttribute(step_kernel,
                         cudaFuncAttributeMaxDynamicSharedMemorySize, SMEM_BYTES);

    tau_kernel<<<4, 256>>>(w_tau);
    wsplit_kernel<<<(NGRP * NT * UU) / 1024, 1024>>>(Wh);
    init_h_kernel<<<(BB * UU + 255) / 256, 256>>>(h0);
    xpre_gemm_kernel<<<dim3(32, 256), 256>>>(features, Wx, bias);

    for (int t = 0; t < TT; t++) {
        step_kernel<<<NGRP, 256, SMEM_BYTES>>>(t, time_steps, out);
    }
}

// round 7
// speedup vs baseline: 1.9329x; 1.5640x over previous
#include <cuda_runtime.h>
#include <cuda_bf16.h>
#include <cstdint>

// Sizes
#define BB 128
#define TT 256
#define DD 256
#define UU 1024
#define N2 2048

// Recurrent-kernel geometry
#define NGRP 64            // blocks; block owns 16 u's -> N=32 cols (16 f + 16 a)
#define NT 32
#define BPAD 1032          // B smem row stride elems
#define BROWB 2064         // B smem row stride bytes
#define ABASE 132096       // A tiles start (after B slab, 128-aligned)
#define ABUFB 32768        // one A buffer (hi 16KB + lo 16KB)
#define SMEM_DYN (ABASE + 2 * ABUFB)   // 197632 B

// ---------------------------------------------------------------------------
// Device scratch (no cudaMalloc allowed)
// ---------------------------------------------------------------------------
__device__ float g_xpre[(size_t)BB * TT * N2];          // x@Wx + b
__device__ float g_h[2][BB * UU];                       // fp32 hidden, ping-pong
__device__ __nv_bfloat16 g_hhi[2][BB * UU];
__device__ __nv_bfloat16 g_hlo[2][BB * UU];
__device__ __nv_bfloat16 g_whi[NGRP * NT * UU];         // Wh repack hi [g][n][k]
__device__ __nv_bfloat16 g_wlo[NGRP * NT * UU];         // Wh repack lo
__device__ float g_tau[UU];

// ---------------------------------------------------------------------------
// PTX helpers (all baseline sm_80/75 ops -- compile for plain sm_103)
// ---------------------------------------------------------------------------
__device__ __forceinline__ uint32_t smem_u32(const void* p) {
    uint32_t a;
    asm("{ .reg .u64 t; cvta.to.shared.u64 t, %1; cvt.u32.u64 %0, t; }"
        : "=r"(a) : "l"(p));
    return a;
}
__device__ __forceinline__ void mma16816(float4& d, const uint32_t* a,
                                         const uint32_t* b) {
    asm volatile(
        "mma.sync.aligned.m16n8k16.row.col.f32.bf16.bf16.f32 "
        "{%0,%1,%2,%3}, {%4,%5,%6,%7}, {%8,%9}, {%0,%1,%2,%3};"
        : "+f"(d.x), "+f"(d.y), "+f"(d.z), "+f"(d.w)
        : "r"(a[0]), "r"(a[1]), "r"(a[2]), "r"(a[3]), "r"(b[0]), "r"(b[1]));
}
#define LDSM4(r0, r1, r2, r3, a)                                        \
    asm volatile("ldmatrix.sync.aligned.m8n8.x4.shared.b16 "            \
                 "{%0,%1,%2,%3}, [%4];"                                 \
                 : "=r"(r0), "=r"(r1), "=r"(r2), "=r"(r3) : "r"(a))
#define CPA16(dst, src)                                                 \
    asm volatile("cp.async.cg.shared.global [%0], [%1], 16;"            \
                 :: "r"(dst), "l"(src))
#define CPA_COMMIT() asm volatile("cp.async.commit_group;" ::: "memory")
#define CPA_WAIT0()  asm volatile("cp.async.wait_group 0;" ::: "memory")

// ---------------------------------------------------------------------------
// Setup kernels
// ---------------------------------------------------------------------------
__global__ void tau_kernel(const float* __restrict__ w_tau) {
    int u = blockIdx.x * blockDim.x + threadIdx.x;
    if (u < UU) g_tau[u] = log1pf(expf(w_tau[u]));
}

__global__ void init_h_kernel(const float* __restrict__ h0) {
    int i = blockIdx.x * blockDim.x + threadIdx.x;
    if (i >= BB * UU) return;
    float v = h0[i];
    g_h[0][i] = v;
    __nv_bfloat16 hi = __float2bfloat16(v);
    g_hhi[0][i] = hi;
    g_hlo[0][i] = __float2bfloat16(v - __bfloat162float(hi));
}

// Wh split+repack: [g][n][k]; n<16 -> f col u=g*16+n; n>=16 -> a col 1024+g*16+n-16
__global__ void wsplit_kernel(const float* __restrict__ Wh) {
    int idx = blockIdx.x * blockDim.x + threadIdx.x;
    if (idx >= NGRP * NT * UU) return;
    int k = idx & (UU - 1);
    int n = (idx >> 10) & (NT - 1);
    int g = idx >> 15;
    int col = (n < 16) ? (g * 16 + n) : (UU + g * 16 + (n - 16));
    float v = Wh[(size_t)k * N2 + col];
    __nv_bfloat16 hi = __float2bfloat16(v);
    g_whi[idx] = hi;
    g_wlo[idx] = __float2bfloat16(v - __bfloat162float(hi));
}

// ---------------------------------------------------------------------------
// xpre GEMM (fp32, known-good): M=32768, N=2048, K=256
// ---------------------------------------------------------------------------
__global__ void __launch_bounds__(256) xpre_gemm_kernel(
    const float* __restrict__ F, const float* __restrict__ Wx,
    const float* __restrict__ bias) {
    __shared__ float As[32][129];
    __shared__ float Bs[32][64];

    int tid = threadIdx.x;
    int bm = blockIdx.y, bn = blockIdx.x;
    int mg = tid >> 4, ng = tid & 15;
    int m0 = mg * 8, n0 = ng * 4;

    const float* Ablk = F + (size_t)bm * 128 * DD;
    const float* Bcol = Wx + bn * 64;

    float acc[8][4];
#pragma unroll
    for (int i = 0; i < 8; i++)
#pragma unroll
        for (int j = 0; j < 4; j++) acc[i][j] = 0.0f;

    for (int k0 = 0; k0 < DD; k0 += 32) {
#pragma unroll
        for (int j = 0; j < 4; j++) {
            int v = tid + 256 * j;
            int kq = v & 7, m = v >> 3;
            float4 a4 = *(const float4*)(Ablk + (size_t)m * DD + k0 + kq * 4);
            As[kq * 4 + 0][m] = a4.x;
            As[kq * 4 + 1][m] = a4.y;
            As[kq * 4 + 2][m] = a4.z;
            As[kq * 4 + 3][m] = a4.w;
        }
#pragma unroll
        for (int j = 0; j < 2; j++) {
            int v = tid + 256 * j;
            int nq = v & 15, k = v >> 4;
            *(float4*)(&Bs[k][nq * 4]) =
                *(const float4*)(Bcol + (size_t)(k0 + k) * N2 + nq * 4);
        }
        __syncthreads();
#pragma unroll 8
        for (int k = 0; k < 32; k++) {
            float bv[4];
            *(float4*)bv = *(const float4*)(&Bs[k][n0]);
            float av[8];
#pragma unroll
            for (int i = 0; i < 8; i++) av[i] = As[k][m0 + i];
#pragma unroll
            for (int i = 0; i < 8; i++)
#pragma unroll
                for (int j = 0; j < 4; j++) acc[i][j] += av[i] * bv[j];
        }
        __syncthreads();
    }
    int nbase = bn * 64 + n0;
    float bv[4];
    *(float4*)bv = *(const float4*)(bias + nbase);
#pragma unroll
    for (int i = 0; i < 8; i++) {
        size_t row = (size_t)bm * 128 + m0 + i;
        float4 o;
        o.x = acc[i][0] + bv[0];
        o.y = acc[i][1] + bv[1];
        o.z = acc[i][2] + bv[2];
        o.w = acc[i][3] + bv[3];
        *(float4*)(&g_xpre[row * N2 + nbase]) = o;
    }
}

// ---------------------------------------------------------------------------
// Recurrent step kernel v3: cp.async-staged A + ldmatrix fragments.
// 64 blocks x 256 threads; warp w owns rows [16w, 16w+16), full K=1024.
// smem: B slab [64 n][BPAD] bf16 (hi rows 0-31, lo 32-63) then 2 A buffers
// (each: hi 128x64 swizzled 16KB + lo 16KB).
// ---------------------------------------------------------------------------
__global__ void __launch_bounds__(256, 1) step_kernel(
    int t, const float* __restrict__ ts, float* __restrict__ out) {
    extern __shared__ __align__(16) char sm[];
    uint32_t s0 = smem_u32(sm);

    int tid = threadIdx.x;
    int wid = tid >> 5, lane = tid & 31;
    int g = blockIdx.x;
    int cur = t & 1, nxt = cur ^ 1;

    const __nv_bfloat16* hh = g_hhi[cur];
    const __nv_bfloat16* hl = g_hlo[cur];
    const __nv_bfloat16* wh = g_whi + (size_t)g * NT * UU;
    const __nv_bfloat16* wl = g_wlo + (size_t)g * NT * UU;

    // ---- Prologue: cp.async B slab (128KB) + A chunk 0, one group ----
#pragma unroll
    for (int p = 0; p < 32; p++) {
        int i = tid + p * 256;
        int np = i >> 7, kc = i & 127;
        const __nv_bfloat16* src =
            (np < 32) ? (wh + np * 1024 + kc * 8) : (wl + (np - 32) * 1024 + kc * 8);
        CPA16(s0 + np * BROWB + kc * 16, src);
    }
#pragma unroll
    for (int p = 0; p < 4; p++) {
        int i = tid + p * 256;
        int row = i >> 3, c8 = i & 7;
        uint32_t d = s0 + ABASE + row * 128 + ((c8 ^ (row & 7)) << 4);
        CPA16(d, hh + row * 1024 + c8 * 8);
        CPA16(d + 16384, hl + row * 1024 + c8 * 8);
    }
    CPA_COMMIT();

    // ---- Per-lane fragment address constants ----
    int arow = wid * 16 + (lane & 15);
    uint32_t aoff = (uint32_t)arow * 128;
    int axor = arow & 7;
    int aco = lane >> 4;                       // 0/1: k16 low/high 8
    int bn = (lane & 7) + ((lane & 16) >> 1);  // 0..15
    int bco = (lane >> 3) & 1;
    uint32_t bbase = s0 + bn * BROWB;

    float4 acc[4];
#pragma unroll
    for (int nt = 0; nt < 4; nt++) acc[nt] = make_float4(0.f, 0.f, 0.f, 0.f);

    // ---- Main pipeline: 16 chunks of 64 k ----
    for (int c = 0; c < 16; c++) {
        CPA_WAIT0();
        __syncthreads();
        if (c < 15) {
            int cn = c + 1;
            uint32_t ab = ABASE + (cn & 1) * ABUFB;
#pragma unroll
            for (int p = 0; p < 4; p++) {
                int i = tid + p * 256;
                int row = i >> 3, c8 = i & 7;
                uint32_t d = s0 + ab + row * 128 + ((c8 ^ (row & 7)) << 4);
                CPA16(d, hh + row * 1024 + cn * 64 + c8 * 8);
                CPA16(d + 16384, hl + row * 1024 + cn * 64 + c8 * 8);
            }
            CPA_COMMIT();
        }

        uint32_t abuf = s0 + ABASE + (c & 1) * ABUFB;
#pragma unroll
        for (int ks = 0; ks < 4; ks++) {
            int ksg = c * 4 + ks;
            uint32_t ah[4], al[4];
            uint32_t aaddr = abuf + aoff + (((ks * 2 + aco) ^ axor) << 4);
            LDSM4(ah[0], ah[1], ah[2], ah[3], aaddr);
            LDSM4(al[0], al[1], al[2], al[3], aaddr + 16384);

            uint32_t cb = (uint32_t)(ksg * 2 + bco) << 4;
            uint32_t bh0[4], bh1[4], bl0[4], bl1[4];
            LDSM4(bh0[0], bh0[1], bh0[2], bh0[3], bbase + cb);
            LDSM4(bh1[0], bh1[1], bh1[2], bh1[3], bbase + 16 * BROWB + cb);
            LDSM4(bl0[0], bl0[1], bl0[2], bl0[3], bbase + 32 * BROWB + cb);
            LDSM4(bl1[0], bl1[1], bl1[2], bl1[3], bbase + 48 * BROWB + cb);

            // 3-product split-bf16: hi*hi + hi*lo + lo*hi
            mma16816(acc[0], ah, bh0 + 0);
            mma16816(acc[1], ah, bh0 + 2);
            mma16816(acc[2], ah, bh1 + 0);
            mma16816(acc[3], ah, bh1 + 2);
            mma16816(acc[0], ah, bl0 + 0);
            mma16816(acc[1], ah, bl0 + 2);
            mma16816(acc[2], ah, bl1 + 0);
            mma16816(acc[3], ah, bl1 + 2);
            mma16816(acc[0], al, bh0 + 0);
            mma16816(acc[1], al, bh0 + 2);
            mma16816(acc[2], al, bh1 + 0);
            mma16816(acc[3], al, bh1 + 2);
        }
    }

    // ---- LTC epilogue (all 8 warps; thread-local f/a pairing) ----
    int u0 = g * 16;
#pragma unroll
    for (int rr = 0; rr < 2; rr++) {
        int row = wid * 16 + (lane >> 2) + rr * 8;
        float dt = ts[row * TT + t];
#pragma unroll
        for (int nt = 0; nt < 2; nt++) {
            int u = u0 + nt * 8 + (lane & 3) * 2;
            size_t xb = ((size_t)row * TT + t) * N2 + u;
            float2 xf = *(const float2*)(g_xpre + xb);
            float2 xa = *(const float2*)(g_xpre + xb + UU);
            float2 tv = *(const float2*)(g_tau + u);
            float2 hp = *(const float2*)(g_h[cur] + (size_t)row * UU + u);

            float pf0, pf1, pa0, pa1;
            if (rr == 0) {
                pf0 = acc[nt].x;     pf1 = acc[nt].y;
                pa0 = acc[nt + 2].x; pa1 = acc[nt + 2].y;
            } else {
                pf0 = acc[nt].z;     pf1 = acc[nt].w;
                pa0 = acc[nt + 2].z; pa1 = acc[nt + 2].w;
            }
            pf0 += xf.x; pf1 += xf.y;
            pa0 += xa.x; pa1 += xa.y;

            float f0 = 1.0f / (1.0f + expf(-pf0));
            float f1 = 1.0f / (1.0f + expf(-pf1));
            float a0 = tanhf(pa0);
            float a1 = tanhf(pa1);
            float d0 = expf(-dt * (tv.x + f0));
            float d1 = expf(-dt * (tv.y + f1));
            float h0n = (hp.x - a0) * d0 + a0;
            float h1n = (hp.y - a1) * d1 + a1;

            *(float2*)(g_h[nxt] + (size_t)row * UU + u) = make_float2(h0n, h1n);
            *(float2*)(out + ((size_t)row * TT + t) * UU + u) =
                make_float2(h0n, h1n);

            __nv_bfloat16 hi0 = __float2bfloat16(h0n);
            __nv_bfloat16 hi1 = __float2bfloat16(h1n);
            __nv_bfloat162 hhi2;
            hhi2.x = hi0; hhi2.y = hi1;
            *(__nv_bfloat162*)(g_hhi[nxt] + (size_t)row * UU + u) = hhi2;
            __nv_bfloat162 hlo2;
            hlo2.x = __float2bfloat16(h0n - __bfloat162float(hi0));
            hlo2.y = __float2bfloat16(h1n - __bfloat162float(hi1));
            *(__nv_bfloat162*)(g_hlo[nxt] + (size_t)row * UU + u) = hlo2;
        }
    }
}

// ---------------------------------------------------------------------------
// Launch
// ---------------------------------------------------------------------------
extern "C" void kernel_launch(void* const* d_in, const int* in_sizes, int n_in,
                              void* d_out, int out_size) {
    const float* features   = (const float*)d_in[0];
    const float* time_steps = (const float*)d_in[1];
    const float* Wx         = (const float*)d_in[2];
    const float* Wh         = (const float*)d_in[3];
    const float* bias       = (const float*)d_in[4];
    const float* w_tau      = (const float*)d_in[5];
    const float* h0         = (const float*)d_in[6];
    float* out = (float*)d_out;

    cudaFuncSetAttribute(step_kernel,
                         cudaFuncAttributeMaxDynamicSharedMemorySize, SMEM_DYN);

    tau_kernel<<<4, 256>>>(w_tau);
    wsplit_kernel<<<(NGRP * NT * UU) / 1024, 1024>>>(Wh);
    init_h_kernel<<<(BB * UU + 255) / 256, 256>>>(h0);
    xpre_gemm_kernel<<<dim3(32, 256), 256>>>(features, Wx, bias);

    for (int t = 0; t < TT; t++) {
        step_kernel<<<NGRP, 256, SMEM_DYN>>>(t, time_steps, out);
    }
}

// round 16
// speedup vs baseline: 2.2314x; 1.1544x over previous
#include <cuda_runtime.h>
#include <cuda_bf16.h>
#include <cstdint>

// Sizes
#define BB 128
#define TT 256
#define DD 256
#define UU 1024
#define N2 2048

// Recurrent-kernel geometry
#define NGRP 64            // blocks; block owns 16 u's -> N=32 cols (16 f + 16 a)
#define NT 32
#define BPAD 1032          // B smem row stride elems
#define BROWB 2064         // B smem row stride bytes
#define ABASE 132096       // A tiles start (after B slab, 128-aligned)
#define ABUFB 32768        // one A buffer (hi 16KB + lo 16KB)
#define SMEM_DYN (ABASE + 2 * ABUFB)   // 197632 B

// ---------------------------------------------------------------------------
// Device scratch (no cudaMalloc allowed)
// ---------------------------------------------------------------------------
__device__ float g_xpre[(size_t)BB * TT * N2];          // x@Wx + b
__device__ float g_h[2][BB * UU];                       // fp32 hidden, ping-pong
__device__ __nv_bfloat16 g_hhi[2][BB * UU];
__device__ __nv_bfloat16 g_hlo[2][BB * UU];
__device__ __nv_bfloat16 g_whi[NGRP * NT * UU];         // Wh repack hi [g][n][k]
__device__ __nv_bfloat16 g_wlo[NGRP * NT * UU];         // Wh repack lo
__device__ float g_tau[UU];
__device__ unsigned int g_bar;                          // grid barrier counter

// ---------------------------------------------------------------------------
// PTX helpers (all baseline sm_80/75 ops -- compile for plain sm_103)
// ---------------------------------------------------------------------------
__device__ __forceinline__ uint32_t smem_u32(const void* p) {
    uint32_t a;
    asm("{ .reg .u64 t; cvta.to.shared.u64 t, %1; cvt.u32.u64 %0, t; }"
        : "=r"(a) : "l"(p));
    return a;
}
__device__ __forceinline__ void mma16816(float4& d, const uint32_t* a,
                                         const uint32_t* b) {
    asm volatile(
        "mma.sync.aligned.m16n8k16.row.col.f32.bf16.bf16.f32 "
        "{%0,%1,%2,%3}, {%4,%5,%6,%7}, {%8,%9}, {%0,%1,%2,%3};"
        : "+f"(d.x), "+f"(d.y), "+f"(d.z), "+f"(d.w)
        : "r"(a[0]), "r"(a[1]), "r"(a[2]), "r"(a[3]), "r"(b[0]), "r"(b[1]));
}
#define LDSM4(r0, r1, r2, r3, a)                                        \
    asm volatile("ldmatrix.sync.aligned.m8n8.x4.shared.b16 "            \
                 "{%0,%1,%2,%3}, [%4];"                                 \
                 : "=r"(r0), "=r"(r1), "=r"(r2), "=r"(r3) : "r"(a))
#define CPA16(dst, src)                                                 \
    asm volatile("cp.async.cg.shared.global [%0], [%1], 16;"            \
                 :: "r"(dst), "l"(src))
#define CPA_COMMIT() asm volatile("cp.async.commit_group;" ::: "memory")
#define CPA_WAIT0()  asm volatile("cp.async.wait_group 0;" ::: "memory")

// ---------------------------------------------------------------------------
// Setup kernels
// ---------------------------------------------------------------------------
__global__ void zero_bar_kernel() { g_bar = 0u; }

__global__ void tau_kernel(const float* __restrict__ w_tau) {
    int u = blockIdx.x * blockDim.x + threadIdx.x;
    if (u < UU) g_tau[u] = log1pf(expf(w_tau[u]));
}

__global__ void init_h_kernel(const float* __restrict__ h0) {
    int i = blockIdx.x * blockDim.x + threadIdx.x;
    if (i >= BB * UU) return;
    float v = h0[i];
    g_h[0][i] = v;
    __nv_bfloat16 hi = __float2bfloat16(v);
    g_hhi[0][i] = hi;
    g_hlo[0][i] = __float2bfloat16(v - __bfloat162float(hi));
}

// Wh split+repack: [g][n][k]; n<16 -> f col u=g*16+n; n>=16 -> a col 1024+g*16+n-16
__global__ void wsplit_kernel(const float* __restrict__ Wh) {
    int idx = blockIdx.x * blockDim.x + threadIdx.x;
    if (idx >= NGRP * NT * UU) return;
    int k = idx & (UU - 1);
    int n = (idx >> 10) & (NT - 1);
    int g = idx >> 15;
    int col = (n < 16) ? (g * 16 + n) : (UU + g * 16 + (n - 16));
    float v = Wh[(size_t)k * N2 + col];
    __nv_bfloat16 hi = __float2bfloat16(v);
    g_whi[idx] = hi;
    g_wlo[idx] = __float2bfloat16(v - __bfloat162float(hi));
}

// ---------------------------------------------------------------------------
// xpre GEMM (fp32, known-good): M=32768, N=2048, K=256
// ---------------------------------------------------------------------------
__global__ void __launch_bounds__(256) xpre_gemm_kernel(
    const float* __restrict__ F, const float* __restrict__ Wx,
    const float* __restrict__ bias) {
    __shared__ float As[32][129];
    __shared__ float Bs[32][64];

    int tid = threadIdx.x;
    int bm = blockIdx.y, bn = blockIdx.x;
    int mg = tid >> 4, ng = tid & 15;
    int m0 = mg * 8, n0 = ng * 4;

    const float* Ablk = F + (size_t)bm * 128 * DD;
    const float* Bcol = Wx + bn * 64;

    float acc[8][4];
#pragma unroll
    for (int i = 0; i < 8; i++)
#pragma unroll
        for (int j = 0; j < 4; j++) acc[i][j] = 0.0f;

    for (int k0 = 0; k0 < DD; k0 += 32) {
#pragma unroll
        for (int j = 0; j < 4; j++) {
            int v = tid + 256 * j;
            int kq = v & 7, m = v >> 3;
            float4 a4 = *(const float4*)(Ablk + (size_t)m * DD + k0 + kq * 4);
            As[kq * 4 + 0][m] = a4.x;
            As[kq * 4 + 1][m] = a4.y;
            As[kq * 4 + 2][m] = a4.z;
            As[kq * 4 + 3][m] = a4.w;
        }
#pragma unroll
        for (int j = 0; j < 2; j++) {
            int v = tid + 256 * j;
            int nq = v & 15, k = v >> 4;
            *(float4*)(&Bs[k][nq * 4]) =
                *(const float4*)(Bcol + (size_t)(k0 + k) * N2 + nq * 4);
        }
        __syncthreads();
#pragma unroll 8
        for (int k = 0; k < 32; k++) {
            float bv[4];
            *(float4*)bv = *(const float4*)(&Bs[k][n0]);
            float av[8];
#pragma unroll
            for (int i = 0; i < 8; i++) av[i] = As[k][m0 + i];
#pragma unroll
            for (int i = 0; i < 8; i++)
#pragma unroll
                for (int j = 0; j < 4; j++) acc[i][j] += av[i] * bv[j];
        }
        __syncthreads();
    }
    int nbase = bn * 64 + n0;
    float bv[4];
    *(float4*)bv = *(const float4*)(bias + nbase);
#pragma unroll
    for (int i = 0; i < 8; i++) {
        size_t row = (size_t)bm * 128 + m0 + i;
        float4 o;
        o.x = acc[i][0] + bv[0];
        o.y = acc[i][1] + bv[1];
        o.z = acc[i][2] + bv[2];
        o.w = acc[i][3] + bv[3];
        *(float4*)(&g_xpre[row * N2 + nbase]) = o;
    }
}

// ---------------------------------------------------------------------------
// Persistent recurrent kernel: 64 blocks x 256 threads, all 256 steps in one
// launch with a monotonic atomic grid barrier (64 blocks <= 148 SMs, occ=1 ->
// all co-resident, no deadlock). Wh slab loaded into smem ONCE.
// h staging uses cp.async.cg (L2-coherent; safe across barrier iterations).
// ---------------------------------------------------------------------------
__global__ void __launch_bounds__(256, 1) rnn_persist_kernel(
    const float* __restrict__ ts, float* __restrict__ out) {
    extern __shared__ __align__(16) char sm[];
    uint32_t s0 = smem_u32(sm);

    int tid = threadIdx.x;
    int wid = tid >> 5, lane = tid & 31;
    int g = blockIdx.x;

    const __nv_bfloat16* wh = g_whi + (size_t)g * NT * UU;
    const __nv_bfloat16* wl = g_wlo + (size_t)g * NT * UU;

    // ---- B slab (128KB) once ----
#pragma unroll
    for (int p = 0; p < 32; p++) {
        int i = tid + p * 256;
        int np = i >> 7, kc = i & 127;
        const __nv_bfloat16* src =
            (np < 32) ? (wh + np * 1024 + kc * 8) : (wl + (np - 32) * 1024 + kc * 8);
        CPA16(s0 + np * BROWB + kc * 16, src);
    }

    // Per-thread A-staging constants
    int srow = tid >> 3, sc8 = tid & 7;
    uint32_t sd0 = s0 + ABASE + srow * 128 + ((sc8 ^ (srow & 7)) << 4);
    uint32_t soff = (uint32_t)srow * 1024 + sc8 * 8;    // elem offset into h (p stride 32 rows)

    // Per-lane fragment constants
    int arow = wid * 16 + (lane & 15);
    uint32_t aoff = (uint32_t)arow * 128;
    int axor = arow & 7;
    int aco = lane >> 4;
    int bn = (lane & 7) + ((lane & 16) >> 1);
    int bco = (lane >> 3) & 1;
    uint32_t bbase = s0 + bn * BROWB;

    // Epilogue constants
    int u0 = g * 16;
    int erow0 = wid * 16 + (lane >> 2);
    int eu = u0 + (lane & 3) * 2;
    float2 tv0 = *(const float2*)(g_tau + eu);
    float2 tv1 = *(const float2*)(g_tau + eu + 8);

    // Stage A chunk 0 of step 0
    {
        const __nv_bfloat16* hh = g_hhi[0];
        const __nv_bfloat16* hl = g_hlo[0];
#pragma unroll
        for (int p = 0; p < 4; p++) {
            uint32_t d = sd0 + p * 4096;           // 32 rows * 128B
            uint32_t so = soff + p * 32 * 1024;
            CPA16(d, hh + so);
            CPA16(d + 16384, hl + so);
        }
        CPA_COMMIT();
    }

    for (int t = 0; t < TT; t++) {
        int cur = t & 1, nxt = cur ^ 1;
        const __nv_bfloat16* hh = g_hhi[cur];
        const __nv_bfloat16* hl = g_hlo[cur];

        float4 acc[4];
#pragma unroll
        for (int nt = 0; nt < 4; nt++) acc[nt] = make_float4(0.f, 0.f, 0.f, 0.f);

        for (int c = 0; c < 16; c++) {
            CPA_WAIT0();
            __syncthreads();
            if (c < 15) {
                int cn = c + 1;
                uint32_t ab = (cn & 1) * ABUFB;
#pragma unroll
                for (int p = 0; p < 4; p++) {
                    uint32_t d = sd0 + ab + p * 4096;
                    uint32_t so = soff + p * 32 * 1024 + cn * 64;
                    CPA16(d, hh + so);
                    CPA16(d + 16384, hl + so);
                }
                CPA_COMMIT();
            }

            uint32_t abuf = s0 + ABASE + (c & 1) * ABUFB;
#pragma unroll
            for (int ks = 0; ks < 4; ks++) {
                int ksg = c * 4 + ks;
                uint32_t ah[4], al[4];
                uint32_t aaddr = abuf + aoff + (((ks * 2 + aco) ^ axor) << 4);
                LDSM4(ah[0], ah[1], ah[2], ah[3], aaddr);
                LDSM4(al[0], al[1], al[2], al[3], aaddr + 16384);

                uint32_t cb = (uint32_t)(ksg * 2 + bco) << 4;
                uint32_t bh0[4], bh1[4], bl0[4], bl1[4];
                LDSM4(bh0[0], bh0[1], bh0[2], bh0[3], bbase + cb);
                LDSM4(bh1[0], bh1[1], bh1[2], bh1[3], bbase + 16 * BROWB + cb);
                LDSM4(bl0[0], bl0[1], bl0[2], bl0[3], bbase + 32 * BROWB + cb);
                LDSM4(bl1[0], bl1[1], bl1[2], bl1[3], bbase + 48 * BROWB + cb);

                // 3-product split-bf16: hi*hi + hi*lo + lo*hi
                mma16816(acc[0], ah, bh0 + 0);
                mma16816(acc[1], ah, bh0 + 2);
                mma16816(acc[2], ah, bh1 + 0);
                mma16816(acc[3], ah, bh1 + 2);
                mma16816(acc[0], ah, bl0 + 0);
                mma16816(acc[1], ah, bl0 + 2);
                mma16816(acc[2], ah, bl1 + 0);
                mma16816(acc[3], ah, bl1 + 2);
                mma16816(acc[0], al, bh0 + 0);
                mma16816(acc[1], al, bh0 + 2);
                mma16816(acc[2], al, bh1 + 0);
                mma16816(acc[3], al, bh1 + 2);
            }
        }

        // ---- LTC epilogue ----
#pragma unroll
        for (int rr = 0; rr < 2; rr++) {
            int row = erow0 + rr * 8;
            float dt = ts[row * TT + t];
#pragma unroll
            for (int nt = 0; nt < 2; nt++) {
                int u = eu + nt * 8;
                float2 tv = (nt == 0) ? tv0 : tv1;
                size_t xb = ((size_t)row * TT + t) * N2 + u;
                float2 xf = *(const float2*)(g_xpre + xb);
                float2 xa = *(const float2*)(g_xpre + xb + UU);
                float2 hp = *(const float2*)(g_h[cur] + (size_t)row * UU + u);

                float pf0, pf1, pa0, pa1;
                if (rr == 0) {
                    pf0 = acc[nt].x;     pf1 = acc[nt].y;
                    pa0 = acc[nt + 2].x; pa1 = acc[nt + 2].y;
                } else {
                    pf0 = acc[nt].z;     pf1 = acc[nt].w;
                    pa0 = acc[nt + 2].z; pa1 = acc[nt + 2].w;
                }
                pf0 += xf.x; pf1 += xf.y;
                pa0 += xa.x; pa1 += xa.y;

                float f0 = 1.0f / (1.0f + expf(-pf0));
                float f1 = 1.0f / (1.0f + expf(-pf1));
                float a0 = tanhf(pa0);
                float a1 = tanhf(pa1);
                float d0 = expf(-dt * (tv.x + f0));
                float d1 = expf(-dt * (tv.y + f1));
                float h0n = (hp.x - a0) * d0 + a0;
                float h1n = (hp.y - a1) * d1 + a1;

                *(float2*)(g_h[nxt] + (size_t)row * UU + u) =
                    make_float2(h0n, h1n);
                *(float2*)(out + ((size_t)row * TT + t) * UU + u) =
                    make_float2(h0n, h1n);

                __nv_bfloat16 hi0 = __float2bfloat16(h0n);
                __nv_bfloat16 hi1 = __float2bfloat16(h1n);
                __nv_bfloat162 hhi2;
                hhi2.x = hi0; hhi2.y = hi1;
                *(__nv_bfloat162*)(g_hhi[nxt] + (size_t)row * UU + u) = hhi2;
                __nv_bfloat162 hlo2;
                hlo2.x = __float2bfloat16(h0n - __bfloat162float(hi0));
                hlo2.y = __float2bfloat16(h1n - __bfloat162float(hi1));
                *(__nv_bfloat162*)(g_hlo[nxt] + (size_t)row * UU + u) = hlo2;
            }
        }

        // ---- Grid barrier (monotonic counter; all blocks co-resident) ----
        __syncthreads();
        if (tid == 0) {
            __threadfence();
            atomicAdd(&g_bar, 1u);
            unsigned int target = (unsigned)NGRP * (unsigned)(t + 1);
            unsigned int v;
            do {
                asm volatile("ld.global.acquire.gpu.u32 %0, [%1];"
                             : "=r"(v) : "l"(&g_bar));
            } while (v < target);
        }
        __syncthreads();

        // Stage A chunk 0 of next step (after barrier: h[nxt] now complete)
        if (t < TT - 1) {
            const __nv_bfloat16* nh = g_hhi[nxt];
            const __nv_bfloat16* nl = g_hlo[nxt];
#pragma unroll
            for (int p = 0; p < 4; p++) {
                uint32_t d = sd0 + p * 4096;
                uint32_t so = soff + p * 32 * 1024;
                CPA16(d, nh + so);
                CPA16(d + 16384, hl + so);
            }
            CPA_COMMIT();
        }
    }
}

// ---------------------------------------------------------------------------
// Launch
// ---------------------------------------------------------------------------
extern "C" void kernel_launch(void* const* d_in, const int* in_sizes, int n_in,
                              void* d_out, int out_size) {
    const float* features   = (const float*)d_in[0];
    const float* time_steps = (const float*)d_in[1];
    const float* Wx         = (const float*)d_in[2];
    const float* Wh         = (const float*)d_in[3];
    const float* bias       = (const float*)d_in[4];
    const float* w_tau      = (const float*)d_in[5];
    const float* h0         = (const float*)d_in[6];
    float* out = (float*)d_out;

    cudaFuncSetAttribute(rnn_persist_kernel,
                         cudaFuncAttributeMaxDynamicSharedMemorySize, SMEM_DYN);

    zero_bar_kernel<<<1, 1>>>();
    tau_kernel<<<4, 256>>>(w_tau);
    wsplit_kernel<<<(NGRP * NT * UU) / 1024, 1024>>>(Wh);
    init_h_kernel<<<(BB * UU + 255) / 256, 256>>>(h0);
    xpre_gemm_kernel<<<dim3(32, 256), 256>>>(features, Wx, bias);

    rnn_persist_kernel<<<NGRP, 256, SMEM_DYN>>>(time_steps, out);
}